// round 11
// baseline (speedup 1.0000x reference)
#include <cuda_runtime.h>

// Linear-chain CRF NLL: fused forward (log-partition) + gold score.
// B=4096, L=1024, T=32. ONE batch per 32-thread block -> 4096 warps,
// ~28 warps/SM (one wave). f32x2 halves = even/odd PREV states:
// fv stored in SMEM as natural float pairs (no duplication), lane l=(j,h)
// computes rows j and j+16 over prev-half [16h,16h+16) with 16 fma2
// (the algebraic floor), folds even/odd, exchanges one scalar via
// shfl_xor 16, applies exp(feat), exact power-of-2 renorm every 4 steps,
// one coalesced STS.32. Emission gold fused in-loop (feat already in reg);
// transition gold in a short bulk phase after the loop.

namespace {

constexpr int T_ = 32;
constexpr int L_ = 1024;
constexpr int START_ = 30;
constexpr int STOP_ = 31;
constexpr unsigned FULL_ = 0xffffffffu;
typedef unsigned long long u64;

__device__ __forceinline__ u64 pack2(float lo, float hi) {
    u64 r;
    asm("mov.b64 %0, {%1, %2};" : "=l"(r) : "f"(lo), "f"(hi));
    return r;
}
__device__ __forceinline__ void unpack2(u64 v, float& lo, float& hi) {
    asm("mov.b64 {%0, %1}, %2;" : "=f"(lo), "=f"(hi) : "l"(v));
}
__device__ __forceinline__ void fma2(u64& acc, u64 a, u64 b) {
    asm("fma.rn.f32x2 %0, %1, %2, %0;" : "+l"(acc) : "l"(a), "l"(b));
}

template <int TS>
__device__ __forceinline__ void crf_body(const float* __restrict__ feats,
                                         const float* __restrict__ trans,
                                         const unsigned* __restrict__ tagw,
                                         float* __restrict__ out,
                                         float (*sv)[32]) {
    const int t = threadIdx.x;
    const int j = t & 15;
    const int h = t >> 4;
    const int b = blockIdx.x;

    // E2[s][k] = {exp(trans[j+16s][16h+2k]), exp(trans[j+16s][16h+2k+1])}
    u64 E2[2][8];
#pragma unroll
    for (int s = 0; s < 2; ++s) {
        const float* tr = trans + (j + 16 * s) * T_ + 16 * h;
#pragma unroll
        for (int k = 0; k < 8; ++k)
            E2[s][k] = pack2(__expf(__ldg(tr + 2 * k)), __expf(__ldg(tr + 2 * k + 1)));
    }

    // Initial fv (linear domain): v[START]=1, else 0. Lane t owns state t.
    sv[0][t] = (t == START_) ? 1.0f : 0.0f;

    const float* fb = feats + (size_t)b * L_ * T_ + t;
    const unsigned* tb = tagw + (size_t)b * L_ * TS;

    float F[3][4];   // feat prefetch [buf][step]
    unsigned P[3];   // 4 tags byte-packed per buf
    int sc = 0;      // log2 scale accumulator
    float ge = 0.f;  // gold emission partial (this lane's state)
    float vcur = 0.f;

#define PF(I, G)                                                               \
    do {                                                                       \
        const int gc_ = ((G) < 256) ? (G) : 255;                               \
        const float* q_ = fb + gc_ * 128;                                      \
        _Pragma("unroll") for (int s_ = 0; s_ < 4; ++s_)                       \
            F[I][s_] = __ldg(q_ + s_ * 32);                                    \
        if (TS == 1) {                                                         \
            uint4 w_ = __ldg((const uint4*)(tb + gc_ * 4));                    \
            P[I] = w_.x | (w_.y << 8) | (w_.z << 16) | (w_.w << 24);           \
        } else {                                                               \
            uint4 a_ = __ldg((const uint4*)(tb + gc_ * 8));                    \
            uint4 c_ = __ldg((const uint4*)(tb + gc_ * 8 + 4));                \
            P[I] = a_.x | (a_.z << 8) | (c_.x << 16) | (c_.z << 24);           \
        }                                                                      \
    } while (0)

#define STEP(I, S, CUR, NXT, RN)                                               \
    do {                                                                       \
        const float f_ = F[I][S];                                              \
        const float ef_ = __expf(f_);                                          \
        const ulonglong2* base_ = (const ulonglong2*)&sv[CUR][h * 16];         \
        const ulonglong2 w0_ = base_[0];                                       \
        const ulonglong2 w1_ = base_[1];                                       \
        const ulonglong2 w2_ = base_[2];                                       \
        const ulonglong2 w3_ = base_[3];                                       \
        u64 a0_ = 0ULL, a1_ = 0ULL;                                            \
        fma2(a0_, w0_.x, E2[0][0]); fma2(a1_, w0_.x, E2[1][0]);                \
        fma2(a0_, w0_.y, E2[0][1]); fma2(a1_, w0_.y, E2[1][1]);                \
        fma2(a0_, w1_.x, E2[0][2]); fma2(a1_, w1_.x, E2[1][2]);                \
        fma2(a0_, w1_.y, E2[0][3]); fma2(a1_, w1_.y, E2[1][3]);                \
        fma2(a0_, w2_.x, E2[0][4]); fma2(a1_, w2_.x, E2[1][4]);                \
        fma2(a0_, w2_.y, E2[0][5]); fma2(a1_, w2_.y, E2[1][5]);                \
        fma2(a0_, w3_.x, E2[0][6]); fma2(a1_, w3_.x, E2[1][6]);                \
        fma2(a0_, w3_.y, E2[0][7]); fma2(a1_, w3_.y, E2[1][7]);                \
        float l0_, h0_, l1_, h1_;                                              \
        unpack2(a0_, l0_, h0_);                                                \
        unpack2(a1_, l1_, h1_);                                                \
        const float r0_ = l0_ + h0_; /* partial of row j     over my prevs */  \
        const float r1_ = l1_ + h1_; /* partial of row j+16  over my prevs */  \
        const float mine_ = h ? r1_ : r0_;                                     \
        const float send_ = h ? r0_ : r1_;                                     \
        float v_ = mine_ + __shfl_xor_sync(FULL_, send_, 16);                  \
        v_ *= ef_;                                                             \
        if (RN) {                                                              \
            unsigned m_ = __reduce_max_sync(FULL_, __float_as_uint(v_));       \
            int e_ = (int)(m_ >> 23) - 127;                                    \
            e_ = max(-64, min(e_, 120));                                       \
            v_ *= __uint_as_float((unsigned)(127 - e_) << 23);                 \
            sc += e_;                                                          \
        }                                                                      \
        vcur = v_;                                                             \
        sv[NXT][t] = v_;                                                       \
        const unsigned g_ = (P[I] >> (8 * (S))) & 0xffu;                       \
        ge += (t == (int)g_) ? f_ : 0.0f;                                      \
        __syncthreads();                                                       \
    } while (0)

#define GROUP(I)                                                               \
    do {                                                                       \
        STEP(I, 0, 0, 1, false);                                               \
        STEP(I, 1, 1, 0, false);                                               \
        STEP(I, 2, 0, 1, false);                                               \
        STEP(I, 3, 1, 0, true);                                                \
    } while (0)

    // Prologue: fill the three prefetch buffers, make init stores visible.
    PF(0, 0);
    PF(1, 1);
    PF(2, 2);
    __syncthreads();

    GROUP(0);  // steps 0..3, works directly off the init fv

    // Groups 1..255, 3-phase rotation, prefetch 2 groups ahead.
#pragma unroll 1
    for (int it = 0; it < 85; ++it) {
        const int gg = 1 + it * 3;
        PF(0, gg + 2);
        GROUP(1);
        PF(1, gg + 3);
        GROUP(2);
        PF(2, gg + 4);
        GROUP(0);
    }

#undef PF
#undef STEP
#undef GROUP

    // ---- bulk gold transition score: sum_l trans[g_l, g_{l-1}] (+STOP term).
    // Lanes sweep 32 consecutive l per iteration; shfl_up provides g_{l-1}.
    float gt = 0.f;
    {
        unsigned carry = START_;
#pragma unroll 4
        for (int it = 0; it < 32; ++it) {
            const int l = it * 32 + t;
            unsigned g = (TS == 1) ? __ldg(tb + l) : __ldg(tb + 2 * l);
            unsigned prev = __shfl_up_sync(FULL_, g, 1);
            if (t == 0) prev = carry;
            carry = __shfl_sync(FULL_, g, 31);
            gt += __ldg(trans + g * 32u + prev);
        }
        if (t == 0) gt += __ldg(trans + STOP_ * 32u + carry);
    }

    // ---- epilogue: alpha = log( sum_t v[t]*exp(trans[STOP,t]) ) + sc*ln2 ----
    float v = vcur * __expf(__ldg(trans + STOP_ * T_ + t));
    float gold = ge + gt;
#pragma unroll
    for (int o = 16; o > 0; o >>= 1) {
        v += __shfl_xor_sync(FULL_, v, o);
        gold += __shfl_xor_sync(FULL_, gold, o);
    }

    if (t == 0) {
        const float LN2 = 0.6931471805599453f;
        out[b] = __logf(v) + (float)sc * LN2 - gold;
    }
}

__global__ void __launch_bounds__(32, 28) crf_fwd(const float* __restrict__ feats,
                                                  const float* __restrict__ trans,
                                                  const unsigned* __restrict__ tagw,
                                                  float* __restrict__ out) {
    __shared__ __align__(16) float sv[2][32];
    // Tag dtype detection: int64 tags (values < 30) have all-zero odd words.
    unsigned oddw = __ldg(tagw + 2 * threadIdx.x + 1);
    if (__any_sync(FULL_, oddw != 0)) {
        crf_body<1>(feats, trans, tagw, out, sv);  // int32 tags
    } else {
        crf_body<2>(feats, trans, tagw, out, sv);  // int64 tags
    }
}

}  // namespace

extern "C" void kernel_launch(void* const* d_in, const int* in_sizes, int n_in,
                              void* d_out, int out_size) {
    const float* feats = (const float*)d_in[0];
    const float* trans = (const float*)d_in[1];
    const unsigned* tagw = (const unsigned*)d_in[2];
    float* out = (float*)d_out;

    const int B = in_sizes[2] / L_;  // element count = B*L for either tag dtype
    crf_fwd<<<B, 32>>>(feats, trans, tagw, out);
}